// round 15
// baseline (speedup 1.0000x reference)
#include <cuda_runtime.h>
#include <cuda_fp16.h>
#include <cstdint>

#define BB 512
#define SS 64
#define DD 256
#define NN 100000
#define NM1 99999
#define D2 512
#define NBLK2 1563          // ceil(99999/64)

// ---- scratch (device globals: no allocation allowed) ----
__device__ __half g_av_h[BB * D2];
__device__ __half g_h_h[BB * D2];
__device__ __half g_lasth_h[BB * DD];
__device__ __half g_W1t[D2 * D2];
__device__ __half g_W2t[DD * D2];
__device__ __half g_emb_h[NN * DD];
__device__ float  g_lse[BB];
__device__ float  g_pmax[BB * NBLK2];
__device__ float  g_psum[BB * NBLK2];
__device__ float  g_logits_fb[BB * NM1];

// ============================================================================
// K-1a: convert embedding fp32 -> fp16
// ============================================================================
__global__ void k_cvt(const float* __restrict__ src, __half* __restrict__ dst, int n4) {
    int i = blockIdx.x * blockDim.x + threadIdx.x;
    int stride = gridDim.x * blockDim.x;
    const float4* s4 = (const float4*)src;
    __half2* d2 = (__half2*)dst;
    for (; i < n4; i += stride) {
        float4 v = s4[i];
        d2[2 * i]     = __floats2half2_rn(v.x, v.y);
        d2[2 * i + 1] = __floats2half2_rn(v.z, v.w);
    }
}

// ============================================================================
// K-1b: W [K,N] fp32 -> W^T [N,K] fp16
// ============================================================================
__global__ void k_wT(const float* __restrict__ src, __half* __restrict__ dst,
                     int K, int N) {
    __shared__ float tile[32][33];
    int tx = threadIdx.x, ty = threadIdx.y;
    int bx = blockIdx.x * 32, by = blockIdx.y * 32;
#pragma unroll
    for (int i = 0; i < 32; i += 8)
        tile[ty + i][tx] = src[(size_t)(by + ty + i) * N + bx + tx];
    __syncthreads();
#pragma unroll
    for (int i = 0; i < 32; i += 8)
        dst[(size_t)(bx + ty + i) * K + by + tx] = __float2half_rn(tile[tx][ty + i]);
}

// ============================================================================
// K0: session length -> last id -> gather + dual adjacency row-aggregation
// ============================================================================
__global__ void k_avlast(const float* __restrict__ emb,
                         const float* __restrict__ adj_in,
                         const float* __restrict__ adj_out,
                         const float* __restrict__ mask,
                         const int* __restrict__ item,
                         const int* __restrict__ alias_) {
    int b = blockIdx.x, t = threadIdx.x;
    __shared__ float ain[SS], aout[SS];
    __shared__ int items[SS];
    __shared__ int s_last;
    if (t == 0) {
        float s = 0.f;
        for (int i = 0; i < SS; i++) s += mask[b * SS + i];
        int rm = (int)s;
        s_last = alias_[b * SS + rm - 1];
    }
    __syncthreads();
    int last = s_last;
    if (t < SS) {
        ain[t]   = adj_in [((size_t)b * SS + last) * SS + t];
        aout[t]  = adj_out[((size_t)b * SS + last) * SS + t];
        items[t] = item[b * SS + t];
    }
    __syncthreads();
    int d = t;
    float aI = 0.f, aO = 0.f;
#pragma unroll 8
    for (int k = 0; k < SS; k++) {
        float e = emb[(size_t)items[k] * DD + d];
        aI = fmaf(ain[k],  e, aI);
        aO = fmaf(aout[k], e, aO);
    }
    g_av_h[b * D2 + d]      = __float2half_rn(aI);
    g_av_h[b * D2 + DD + d] = __float2half_rn(aO);
}

// ============================================================================
// K1/K2: fp16 tensor-core GEMM  C[M,N] = A[M,K] @ B[N,K]^T  (proven R14)
// ============================================================================
#define GP 144
#define GA_B (128 * GP)
#define GB_B (64 * GP)
#define GSTG (GA_B + GB_B)
#define SMEM_G16 (2 * GSTG)

__device__ __forceinline__ void mma_f16(float* c, uint32_t a0, uint32_t a1,
                                        uint32_t a2, uint32_t a3,
                                        uint32_t b0, uint32_t b1) {
    asm volatile("mma.sync.aligned.m16n8k16.row.col.f32.f16.f16.f32 "
                 "{%0,%1,%2,%3},{%4,%5,%6,%7},{%8,%9},{%0,%1,%2,%3};"
                 : "+f"(c[0]), "+f"(c[1]), "+f"(c[2]), "+f"(c[3])
                 : "r"(a0), "r"(a1), "r"(a2), "r"(a3), "r"(b0), "r"(b1));
}

__global__ __launch_bounds__(256) void k_gemm16(const __half* __restrict__ A,
                                                const __half* __restrict__ B,
                                                __half* __restrict__ C,
                                                int K, int N, int relu, int nchunk) {
    extern __shared__ char gsm[];
    uint32_t sbase = (uint32_t)__cvta_generic_to_shared(gsm);
    int row0 = blockIdx.y * 128, col0 = blockIdx.x * 64;
    int t = threadIdx.x;
    int warp = t >> 5, lane = t & 31;
    int wm = warp >> 1, wn = warp & 1;
    int g = lane >> 2, tq = lane & 3;
    int lr = lane & 7, bq = lane >> 3;
    int rowadd = lr + ((bq & 1) << 3);
    int coladdB = (bq >> 1) << 4;

    uint32_t offA[2], offB[2];
#pragma unroll
    for (int mi = 0; mi < 2; mi++)
        offA[mi] = (uint32_t)((wm * 32 + mi * 16 + rowadd) * GP + coladdB);
#pragma unroll
    for (int np = 0; np < 2; np++)
        offB[np] = (uint32_t)((wn * 32 + np * 16 + rowadd) * GP + coladdB);

    float c[2][4][4];
#pragma unroll
    for (int mi = 0; mi < 2; mi++)
#pragma unroll
        for (int nf = 0; nf < 4; nf++)
#pragma unroll
            for (int q = 0; q < 4; q++) c[mi][nf][q] = 0.f;

    int rA = t >> 3, cA16 = t & 7;
    {
#pragma unroll
        for (int u0 = 0; u0 < 4; u0++) {
            int r = rA + u0 * 32;
            asm volatile("cp.async.cg.shared.global [%0], [%1], 16;\n"
                :: "r"(sbase + (uint32_t)(r * GP + cA16 * 16)),
                   "l"(A + (size_t)(row0 + r) * K + cA16 * 8));
        }
#pragma unroll
        for (int u0 = 0; u0 < 2; u0++) {
            int r = rA + u0 * 32;
            asm volatile("cp.async.cg.shared.global [%0], [%1], 16;\n"
                :: "r"(sbase + (uint32_t)(GA_B + r * GP + cA16 * 16)),
                   "l"(B + (size_t)(col0 + r) * K + cA16 * 8));
        }
        asm volatile("cp.async.commit_group;");
    }

    for (int s = 0; s < nchunk; s++) {
        if (s + 1 < nchunk) {
            uint32_t dst = sbase + ((s + 1) & 1) * GSTG;
            int k0 = (s + 1) * 64;
#pragma unroll
            for (int u0 = 0; u0 < 4; u0++) {
                int r = rA + u0 * 32;
                asm volatile("cp.async.cg.shared.global [%0], [%1], 16;\n"
                    :: "r"(dst + (uint32_t)(r * GP + cA16 * 16)),
                       "l"(A + (size_t)(row0 + r) * K + k0 + cA16 * 8));
            }
#pragma unroll
            for (int u0 = 0; u0 < 2; u0++) {
                int r = rA + u0 * 32;
                asm volatile("cp.async.cg.shared.global [%0], [%1], 16;\n"
                    :: "r"(dst + (uint32_t)(GA_B + r * GP + cA16 * 16)),
                       "l"(B + (size_t)(col0 + r) * K + k0 + cA16 * 8));
            }
        }
        asm volatile("cp.async.commit_group;");
        asm volatile("cp.async.wait_group 1;");
        __syncthreads();
        uint32_t cAb = sbase + (s & 1) * GSTG;
        uint32_t cBb = cAb + GA_B;
#pragma unroll
        for (int ks = 0; ks < 4; ks++) {
            uint32_t kb = (uint32_t)(ks * 32);
            uint32_t a[2][4];
#pragma unroll
            for (int mi = 0; mi < 2; mi++) {
                asm volatile("ldmatrix.sync.aligned.m8n8.x4.shared.b16 {%0,%1,%2,%3}, [%4];"
                             : "=r"(a[mi][0]), "=r"(a[mi][1]), "=r"(a[mi][2]), "=r"(a[mi][3])
                             : "r"(cAb + offA[mi] + kb));
            }
#pragma unroll
            for (int np = 0; np < 2; np++) {
                uint32_t b0, b1, b2r, b3;
                asm volatile("ldmatrix.sync.aligned.m8n8.x4.shared.b16 {%0,%1,%2,%3}, [%4];"
                             : "=r"(b0), "=r"(b1), "=r"(b2r), "=r"(b3)
                             : "r"(cBb + offB[np] + kb));
#pragma unroll
                for (int mi = 0; mi < 2; mi++) {
                    mma_f16(c[mi][2 * np],     a[mi][0], a[mi][1], a[mi][2], a[mi][3], b0, b2r);
                    mma_f16(c[mi][2 * np + 1], a[mi][0], a[mi][1], a[mi][2], a[mi][3], b1, b3);
                }
            }
        }
        __syncthreads();
    }

#pragma unroll
    for (int mi = 0; mi < 2; mi++) {
        int r0 = row0 + wm * 32 + mi * 16 + g;
#pragma unroll
        for (int nf = 0; nf < 4; nf++) {
            int c0 = col0 + wn * 32 + nf * 8 + 2 * tq;
            float v0 = c[mi][nf][0], v1 = c[mi][nf][1];
            float v2 = c[mi][nf][2], v3 = c[mi][nf][3];
            if (relu) {
                v0 = fmaxf(v0, 0.f); v1 = fmaxf(v1, 0.f);
                v2 = fmaxf(v2, 0.f); v3 = fmaxf(v3, 0.f);
            }
            *(__half2*)&C[(size_t)r0 * N + c0]       = __floats2half2_rn(v0, v1);
            *(__half2*)&C[(size_t)(r0 + 8) * N + c0] = __floats2half2_rn(v2, v3);
        }
    }
}

// ============================================================================
// K3: logits = last_h[512,256] @ emb[1:].T  (FP16 mma m16n8k16)
//     128x64 tile (32 accs/thread), 8 warps (4M x 2N, warp tile 32x32),
//     2-stage mbarrier pipeline, __launch_bounds__(256,3) -> 3 CTAs/SM,
//     fused per-row (max,sumexp) partials over 64-col blocks.
// ============================================================================
__device__ __forceinline__ void mbar_wait(uint32_t addr, uint32_t parity) {
    asm volatile(
        "{\n\t.reg .pred P;\n\t"
        "WL%=:\n\t"
        "mbarrier.try_wait.parity.acquire.cta.shared::cta.b64 P, [%0], %1, 0x989680;\n\t"
        "@P bra.uni DN%=;\n\t"
        "bra.uni WL%=;\n\t"
        "DN%=:\n\t}"
        :: "r"(addr), "r"(parity) : "memory");
}

#define PITCHB 144
#define LA_B (128 * PITCHB)            // A stage bytes (18432)
#define LB_B (64 * PITCHB)             // B stage bytes (9216)
#define LSTG (LA_B + LB_B)             // 27648
#define NSTL 2
#define NCHUNK 4
#define SM_CTRL 1024
#define SMEM_LOGITS_BYTES (SM_CTRL + NSTL * LSTG)   // 56320

__device__ __forceinline__ void stage_logits(uint32_t sA, uint32_t sB,
                                             const __half* __restrict__ Ah,
                                             const __half* __restrict__ embh,
                                             int mt, int nt, int k0, int t) {
    int rA = t >> 3, c16 = t & 7;
#pragma unroll
    for (int u0 = 0; u0 < 4; u0++) {
        int r = rA + u0 * 32;
        asm volatile("cp.async.cg.shared.global [%0], [%1], 16;\n"
                     :: "r"(sA + (uint32_t)(r * PITCHB + c16 * 16)),
                        "l"(Ah + (size_t)(mt + r) * DD + k0 + c16 * 8));
    }
#pragma unroll
    for (int u0 = 0; u0 < 2; u0++) {
        int r = rA + u0 * 32;
        int er = nt + 1 + r;
        const __half* srcB = embh + (size_t)(er < NN ? er : 0) * DD + k0 + c16 * 8;
        int sz = (er < NN) ? 16 : 0;
        asm volatile("cp.async.cg.shared.global [%0], [%1], 16, %2;\n"
                     :: "r"(sB + (uint32_t)(r * PITCHB + c16 * 16)), "l"(srcB), "r"(sz));
    }
}

__global__ __launch_bounds__(256, 3) void k_logits(const __half* __restrict__ Ah,
                                                   const __half* __restrict__ embh,
                                                   float* __restrict__ out) {
    extern __shared__ float smem[];
    uint32_t sbase = (uint32_t)__cvta_generic_to_shared(smem);
    uint32_t mfull[NSTL], mempty[NSTL];
#pragma unroll
    for (int i = 0; i < NSTL; i++) { mfull[i] = sbase + 16 * i; mempty[i] = sbase + 16 * i + 8; }
    uint32_t sA[NSTL], sB[NSTL];
#pragma unroll
    for (int i = 0; i < NSTL; i++) {
        sA[i] = sbase + SM_CTRL + i * LSTG;
        sB[i] = sA[i] + LA_B;
    }

    int mt = blockIdx.x * 128;
    int nt = blockIdx.y * 64;
    int t = threadIdx.x;
    int warp = t >> 5, lane = t & 31;
    int wm = warp >> 1, wn = warp & 1;
    int g = lane >> 2, tq = lane & 3;
    int lr = lane & 7, bq = lane >> 3;
    int rowadd = lr + ((bq & 1) << 3);
    int coladdB = (bq >> 1) << 4;

    uint32_t offA[2], offB[2];
#pragma unroll
    for (int mi = 0; mi < 2; mi++)
        offA[mi] = (uint32_t)((wm * 32 + mi * 16 + rowadd) * PITCHB + coladdB);
#pragma unroll
    for (int np = 0; np < 2; np++)
        offB[np] = (uint32_t)((wn * 32 + np * 16 + rowadd) * PITCHB + coladdB);

    float c[2][4][4];
#pragma unroll
    for (int mi = 0; mi < 2; mi++)
#pragma unroll
        for (int nf = 0; nf < 4; nf++)
#pragma unroll
            for (int q = 0; q < 4; q++) c[mi][nf][q] = 0.f;

    if (t == 0) {
#pragma unroll
        for (int i = 0; i < NSTL; i++) {
            asm volatile("mbarrier.init.shared.b64 [%0], 256;" :: "r"(mfull[i])  : "memory");
            asm volatile("mbarrier.init.shared.b64 [%0], 8;"   :: "r"(mempty[i]) : "memory");
        }
    }
    __syncthreads();

    stage_logits(sA[0], sB[0], Ah, embh, mt, nt, 0, t);
    asm volatile("cp.async.mbarrier.arrive.noinc.shared.b64 [%0];" :: "r"(mfull[0]) : "memory");

    for (int s = 0; s < NCHUNK; s++) {
        int u = s + 1;
        if (u < NCHUNK) {
            int b2 = u & 1;
            if (u >= NSTL)
                mbar_wait(mempty[b2], (uint32_t)(((u - NSTL) / NSTL) & 1));
            stage_logits(sA[b2], sB[b2], Ah, embh, mt, nt, u * 64, t);
            asm volatile("cp.async.mbarrier.arrive.noinc.shared.b64 [%0];"
                         :: "r"(mfull[b2]) : "memory");
        }
        int b = s & 1;
        mbar_wait(mfull[b], (uint32_t)((s / NSTL) & 1));
        uint32_t cA = sA[b], cB = sB[b];
#pragma unroll
        for (int ks = 0; ks < 4; ks++) {
            uint32_t kb = (uint32_t)(ks * 32);
            uint32_t a[2][4];
#pragma unroll
            for (int mi = 0; mi < 2; mi++) {
                asm volatile("ldmatrix.sync.aligned.m8n8.x4.shared.b16 {%0,%1,%2,%3}, [%4];"
                             : "=r"(a[mi][0]), "=r"(a[mi][1]), "=r"(a[mi][2]), "=r"(a[mi][3])
                             : "r"(cA + offA[mi] + kb));
            }
#pragma unroll
            for (int np = 0; np < 2; np++) {
                uint32_t b0, b1, b2r, b3;
                asm volatile("ldmatrix.sync.aligned.m8n8.x4.shared.b16 {%0,%1,%2,%3}, [%4];"
                             : "=r"(b0), "=r"(b1), "=r"(b2r), "=r"(b3)
                             : "r"(cB + offB[np] + kb));
#pragma unroll
                for (int mi = 0; mi < 2; mi++) {
                    mma_f16(c[mi][2 * np],     a[mi][0], a[mi][1], a[mi][2], a[mi][3], b0, b2r);
                    mma_f16(c[mi][2 * np + 1], a[mi][0], a[mi][1], a[mi][2], a[mi][3], b1, b3);
                }
            }
        }
        if (lane == 0)
            asm volatile("mbarrier.arrive.shared.b64 _, [%0];" :: "r"(mempty[b]) : "memory");
    }

    // ---- logits stores ----
#pragma unroll
    for (int mi = 0; mi < 2; mi++) {
        int r0 = mt + wm * 32 + mi * 16 + g;
#pragma unroll
        for (int nf = 0; nf < 4; nf++) {
            int c0 = nt + wn * 32 + nf * 8 + 2 * tq;
            if (c0 < NM1) {
                out[(size_t)r0 * NM1 + c0]       = c[mi][nf][0];
                out[(size_t)(r0 + 8) * NM1 + c0] = c[mi][nf][2];
            }
            if (c0 + 1 < NM1) {
                out[(size_t)r0 * NM1 + c0 + 1]       = c[mi][nf][1];
                out[(size_t)(r0 + 8) * NM1 + c0 + 1] = c[mi][nf][3];
            }
        }
    }

    __syncthreads();   // stage buffers dead; reuse smem

    // ---- fused LSE partials over this block's 64 cols ----
    float* redM = smem + 256;
    float* redS = smem + 512;
#pragma unroll
    for (int slot = 0; slot < 4; slot++) {
        int mi = slot >> 1, h = slot & 1;
        float m = -3.0e38f;
#pragma unroll
        for (int nf = 0; nf < 4; nf++) {
            int cbase = nt + wn * 32 + nf * 8 + 2 * tq;
            float v0 = (cbase     < NM1) ? c[mi][nf][2 * h]     : -3.0e38f;
            float v1 = (cbase + 1 < NM1) ? c[mi][nf][2 * h + 1] : -3.0e38f;
            m = fmaxf(m, fmaxf(v0, v1));
        }
        float sum = 0.f;
#pragma unroll
        for (int nf = 0; nf < 4; nf++) {
            int cbase = nt + wn * 32 + nf * 8 + 2 * tq;
            float v0 = (cbase     < NM1) ? c[mi][nf][2 * h]     : -3.0e38f;
            float v1 = (cbase + 1 < NM1) ? c[mi][nf][2 * h + 1] : -3.0e38f;
            sum += __expf(v0 - m) + __expf(v1 - m);
        }
#pragma unroll
        for (int off = 1; off <= 2; off <<= 1) {
            float m2 = __shfl_xor_sync(0xffffffffu, m, off);
            float s2 = __shfl_xor_sync(0xffffffffu, sum, off);
            float M = fmaxf(m, m2);
            sum = sum * __expf(m - M) + s2 * __expf(m2 - M);
            m = M;
        }
        if (tq == 0) {
            redM[(warp * 4 + slot) * 8 + g] = m;
            redS[(warp * 4 + slot) * 8 + g] = sum;
        }
    }
    __syncthreads();
    if (t < 128) {
        int wmr = t >> 5, slot = (t >> 3) & 3, gg = t & 7;
        int i1 = ((wmr * 2)     * 4 + slot) * 8 + gg;   // wn=0 warp
        int i2 = ((wmr * 2 + 1) * 4 + slot) * 8 + gg;   // wn=1 warp
        float m1 = redM[i1], s1 = redS[i1];
        float m2 = redM[i2], s2 = redS[i2];
        float M = fmaxf(m1, m2);
        float S = s1 * __expf(m1 - M) + s2 * __expf(m2 - M);
        int row = mt + wmr * 32 + (slot >> 1) * 16 + (slot & 1) * 8 + gg;
        g_pmax[(size_t)row * NBLK2 + blockIdx.y] = M;
        g_psum[(size_t)row * NBLK2 + blockIdx.y] = S;
    }
}

// ============================================================================
// K4: finalize LSE from per-block partials
// ============================================================================
__global__ void k_lsefin(float* __restrict__ lse) {
    int b = blockIdx.x, t = threadIdx.x;
    float m = -3.0e38f, s = 0.f;
    for (int i = t; i < NBLK2; i += 256) {
        float m2 = g_pmax[(size_t)b * NBLK2 + i];
        float s2 = g_psum[(size_t)b * NBLK2 + i];
        float M = fmaxf(m, m2);
        s = s * __expf(m - M) + s2 * __expf(m2 - M);
        m = M;
    }
    __shared__ float sm[256], ss[256];
    sm[t] = m; ss[t] = s;
    __syncthreads();
    for (int o = 128; o > 0; o >>= 1) {
        if (t < o) {
            float m2 = sm[t + o], s2 = ss[t + o];
            float M = fmaxf(sm[t], m2);
            ss[t] = ss[t] * __expf(sm[t] - M) + s2 * __expf(m2 - M);
            sm[t] = M;
        }
        __syncthreads();
    }
    if (t == 0) lse[b] = sm[0] + logf(ss[0]);
}

// ============================================================================
// K5: loss = -mean_b( logits[b, tar[b]-1] - lse[b] )
// ============================================================================
__global__ void k_loss(const float* __restrict__ logits, const float* __restrict__ lse,
                       const int* __restrict__ tar, float* __restrict__ loss_out) {
    __shared__ float red[512];
    int t = threadIdx.x;
    int tg = tar[t] - 1;
    red[t] = logits[(size_t)t * NM1 + tg] - lse[t];
    __syncthreads();
    for (int o = 256; o > 0; o >>= 1) {
        if (t < o) red[t] += red[t + o];
        __syncthreads();
    }
    if (t == 0) loss_out[0] = -red[0] / (float)BB;
}

// ============================================================================
// launch
// ============================================================================
extern "C" void kernel_launch(void* const* d_in, const int* in_sizes, int n_in,
                              void* d_out, int out_size) {
    const float* emb    = (const float*)d_in[0];
    const float* W1     = (const float*)d_in[1];
    const float* W2     = (const float*)d_in[2];
    const float* adjI   = (const float*)d_in[3];
    const float* adjO   = (const float*)d_in[4];
    const float* mask   = (const float*)d_in[5];
    const int*   item   = (const int*)d_in[6];
    const int*   alias_ = (const int*)d_in[7];
    const int*   tar    = (const int*)d_in[8];
    float* out = (float*)d_out;

    float *p_lse, *p_fb;
    __half *p_av, *p_hh, *p_lh, *p_eh, *p_w1t, *p_w2t;
    cudaGetSymbolAddress((void**)&p_av,  g_av_h);
    cudaGetSymbolAddress((void**)&p_hh,  g_h_h);
    cudaGetSymbolAddress((void**)&p_lh,  g_lasth_h);
    cudaGetSymbolAddress((void**)&p_eh,  g_emb_h);
    cudaGetSymbolAddress((void**)&p_w1t, g_W1t);
    cudaGetSymbolAddress((void**)&p_w2t, g_W2t);
    cudaGetSymbolAddress((void**)&p_lse, g_lse);
    cudaGetSymbolAddress((void**)&p_fb,  g_logits_fb);

    static int smem_set = 0;
    if (!smem_set) {
        cudaFuncSetAttribute(k_logits, cudaFuncAttributeMaxDynamicSharedMemorySize,
                             SMEM_LOGITS_BYTES);
        cudaFuncSetAttribute(k_gemm16, cudaFuncAttributeMaxDynamicSharedMemorySize,
                             SMEM_G16);
        smem_set = 1;
    }

    const long long NL = (long long)BB * NM1;
    float *loss_ptr, *logits_ptr;
    if ((long long)out_size >= NL + 1)      { loss_ptr = out;  logits_ptr = out + 1; }
    else if ((long long)out_size == NL)     { loss_ptr = p_fb; logits_ptr = out; }
    else                                    { loss_ptr = out;  logits_ptr = p_fb; }

    k_cvt<<<2048, 256>>>(emb, p_eh, NN * DD / 4);
    k_wT<<<dim3(16, 16), dim3(32, 8)>>>(W1, p_w1t, D2, D2);
    k_wT<<<dim3(8, 16),  dim3(32, 8)>>>(W2, p_w2t, D2, DD);
    k_avlast<<<BB, 256>>>(emb, adjI, adjO, mask, item, alias_);
    k_gemm16<<<dim3(D2 / 64, BB / 128), 256, SMEM_G16>>>(p_av, p_w1t, p_hh,
                                                         D2, D2, 1, 8);
    k_gemm16<<<dim3(DD / 64, BB / 128), 256, SMEM_G16>>>(p_hh, p_w2t, p_lh,
                                                         D2, DD, 0, 8);
    k_logits<<<dim3(4, NBLK2), 256, SMEM_LOGITS_BYTES>>>(p_lh, p_eh, logits_ptr);
    k_lsefin<<<BB, 256>>>(p_lse);
    k_loss<<<1, 512>>>(logits_ptr, p_lse, tar, loss_ptr);
}

// round 16
// speedup vs baseline: 1.1020x; 1.1020x over previous
#include <cuda_runtime.h>
#include <cuda_fp16.h>
#include <cstdint>

#define BB 512
#define SS 64
#define DD 256
#define NN 100000
#define NM1 99999
#define D2 512
#define NBLK 782            // ceil(99999/128)

// ---- scratch (device globals: no allocation allowed) ----
__device__ __half g_av_h[BB * D2];
__device__ __half g_h_h[BB * D2];
__device__ __half g_lasth_h[BB * DD];
__device__ __half g_W1t[D2 * D2];
__device__ __half g_W2t[DD * D2];
__device__ __half g_emb_h[NN * DD];
__device__ float  g_lse[BB];
__device__ float  g_pmax[BB * NBLK];
__device__ float  g_psum[BB * NBLK];
__device__ float  g_logits_fb[BB * NM1];

// ============================================================================
// K0: fused prep — emb fp32->fp16 | W1^T | W2^T | avlast, partitioned by CTA.
//     All parts independent; one launch lets them fill the chip concurrently.
//     CTAs: [0,2048) cvt | [2048,2304) W1t | [2304,2432) W2t | [2432,2944) avlast
// ============================================================================
__global__ __launch_bounds__(256) void k_prep(const float* __restrict__ emb,
                                              const float* __restrict__ W1,
                                              const float* __restrict__ W2,
                                              const float* __restrict__ adj_in,
                                              const float* __restrict__ adj_out,
                                              const float* __restrict__ mask,
                                              const int* __restrict__ item,
                                              const int* __restrict__ alias_) {
    __shared__ char sbuf[4352];
    int bid = blockIdx.x, t = threadIdx.x;

    if (bid < 2048) {
        // ---- emb fp32 -> fp16 ----
        const int n4 = NN * DD / 4;
        const float4* s4 = (const float4*)emb;
        __half2* d2 = (__half2*)g_emb_h;
        int stride = 2048 * 256;
        for (int i = bid * 256 + t; i < n4; i += stride) {
            float4 v = s4[i];
            d2[2 * i]     = __floats2half2_rn(v.x, v.y);
            d2[2 * i + 1] = __floats2half2_rn(v.z, v.w);
        }
    } else if (bid < 2432) {
        // ---- weight transpose (32x32 tile) ----
        float (*tile)[33] = (float(*)[33])sbuf;
        const float* src; __half* dst; int K, N, w;
        if (bid < 2304) { src = W1; dst = g_W1t; K = D2; N = D2; w = bid - 2048; }
        else            { src = W2; dst = g_W2t; K = D2; N = DD; w = bid - 2304; }
        int nx = N / 32;
        int bx = (w % nx) * 32, by = (w / nx) * 32;
        int tx = t & 31, ty = t >> 5;            // 32 x 8
#pragma unroll
        for (int i = 0; i < 32; i += 8)
            tile[ty + i][tx] = src[(size_t)(by + ty + i) * N + bx + tx];
        __syncthreads();
#pragma unroll
        for (int i = 0; i < 32; i += 8)
            dst[(size_t)(bx + ty + i) * K + by + tx] = __float2half_rn(tile[tx][ty + i]);
    } else {
        // ---- avlast ----
        int b = bid - 2432;
        float* ain  = (float*)sbuf;
        float* aout = ain + SS;
        int*  items = (int*)(aout + SS);
        int*  plast = items + SS;
        if (t == 0) {
            float s = 0.f;
            for (int i = 0; i < SS; i++) s += mask[b * SS + i];
            int rm = (int)s;
            plast[0] = alias_[b * SS + rm - 1];
        }
        __syncthreads();
        int last = plast[0];
        if (t < SS) {
            ain[t]   = adj_in [((size_t)b * SS + last) * SS + t];
            aout[t]  = adj_out[((size_t)b * SS + last) * SS + t];
            items[t] = item[b * SS + t];
        }
        __syncthreads();
        int d = t;
        float aI = 0.f, aO = 0.f;
#pragma unroll 8
        for (int k = 0; k < SS; k++) {
            float e = emb[(size_t)items[k] * DD + d];
            aI = fmaf(ain[k],  e, aI);
            aO = fmaf(aout[k], e, aO);
        }
        g_av_h[b * D2 + d]      = __float2half_rn(aI);
        g_av_h[b * D2 + DD + d] = __float2half_rn(aO);
    }
}

// ============================================================================
// K1/K2: fp16 tensor-core GEMM  C[M,N] = A[M,K] @ B[N,K]^T  (proven R14)
// ============================================================================
#define GP 144
#define GA_B (128 * GP)
#define GB_B (64 * GP)
#define GSTG (GA_B + GB_B)
#define SMEM_G16 (2 * GSTG)

__device__ __forceinline__ void mma_f16(float* c, uint32_t a0, uint32_t a1,
                                        uint32_t a2, uint32_t a3,
                                        uint32_t b0, uint32_t b1) {
    asm volatile("mma.sync.aligned.m16n8k16.row.col.f32.f16.f16.f32 "
                 "{%0,%1,%2,%3},{%4,%5,%6,%7},{%8,%9},{%0,%1,%2,%3};"
                 : "+f"(c[0]), "+f"(c[1]), "+f"(c[2]), "+f"(c[3])
                 : "r"(a0), "r"(a1), "r"(a2), "r"(a3), "r"(b0), "r"(b1));
}

__global__ __launch_bounds__(256) void k_gemm16(const __half* __restrict__ A,
                                                const __half* __restrict__ B,
                                                __half* __restrict__ C,
                                                int K, int N, int relu, int nchunk) {
    extern __shared__ char gsm[];
    uint32_t sbase = (uint32_t)__cvta_generic_to_shared(gsm);
    int row0 = blockIdx.y * 128, col0 = blockIdx.x * 64;
    int t = threadIdx.x;
    int warp = t >> 5, lane = t & 31;
    int wm = warp >> 1, wn = warp & 1;
    int g = lane >> 2, tq = lane & 3;
    int lr = lane & 7, bq = lane >> 3;
    int rowadd = lr + ((bq & 1) << 3);
    int coladdB = (bq >> 1) << 4;

    uint32_t offA[2], offB[2];
#pragma unroll
    for (int mi = 0; mi < 2; mi++)
        offA[mi] = (uint32_t)((wm * 32 + mi * 16 + rowadd) * GP + coladdB);
#pragma unroll
    for (int np = 0; np < 2; np++)
        offB[np] = (uint32_t)((wn * 32 + np * 16 + rowadd) * GP + coladdB);

    float c[2][4][4];
#pragma unroll
    for (int mi = 0; mi < 2; mi++)
#pragma unroll
        for (int nf = 0; nf < 4; nf++)
#pragma unroll
            for (int q = 0; q < 4; q++) c[mi][nf][q] = 0.f;

    int rA = t >> 3, cA16 = t & 7;
    {
#pragma unroll
        for (int u0 = 0; u0 < 4; u0++) {
            int r = rA + u0 * 32;
            asm volatile("cp.async.cg.shared.global [%0], [%1], 16;\n"
                :: "r"(sbase + (uint32_t)(r * GP + cA16 * 16)),
                   "l"(A + (size_t)(row0 + r) * K + cA16 * 8));
        }
#pragma unroll
        for (int u0 = 0; u0 < 2; u0++) {
            int r = rA + u0 * 32;
            asm volatile("cp.async.cg.shared.global [%0], [%1], 16;\n"
                :: "r"(sbase + (uint32_t)(GA_B + r * GP + cA16 * 16)),
                   "l"(B + (size_t)(col0 + r) * K + cA16 * 8));
        }
        asm volatile("cp.async.commit_group;");
    }

    for (int s = 0; s < nchunk; s++) {
        if (s + 1 < nchunk) {
            uint32_t dst = sbase + ((s + 1) & 1) * GSTG;
            int k0 = (s + 1) * 64;
#pragma unroll
            for (int u0 = 0; u0 < 4; u0++) {
                int r = rA + u0 * 32;
                asm volatile("cp.async.cg.shared.global [%0], [%1], 16;\n"
                    :: "r"(dst + (uint32_t)(r * GP + cA16 * 16)),
                       "l"(A + (size_t)(row0 + r) * K + k0 + cA16 * 8));
            }
#pragma unroll
            for (int u0 = 0; u0 < 2; u0++) {
                int r = rA + u0 * 32;
                asm volatile("cp.async.cg.shared.global [%0], [%1], 16;\n"
                    :: "r"(dst + (uint32_t)(GA_B + r * GP + cA16 * 16)),
                       "l"(B + (size_t)(col0 + r) * K + k0 + cA16 * 8));
            }
        }
        asm volatile("cp.async.commit_group;");
        asm volatile("cp.async.wait_group 1;");
        __syncthreads();
        uint32_t cAb = sbase + (s & 1) * GSTG;
        uint32_t cBb = cAb + GA_B;
#pragma unroll
        for (int ks = 0; ks < 4; ks++) {
            uint32_t kb = (uint32_t)(ks * 32);
            uint32_t a[2][4];
#pragma unroll
            for (int mi = 0; mi < 2; mi++) {
                asm volatile("ldmatrix.sync.aligned.m8n8.x4.shared.b16 {%0,%1,%2,%3}, [%4];"
                             : "=r"(a[mi][0]), "=r"(a[mi][1]), "=r"(a[mi][2]), "=r"(a[mi][3])
                             : "r"(cAb + offA[mi] + kb));
            }
#pragma unroll
            for (int np = 0; np < 2; np++) {
                uint32_t b0, b1, b2r, b3;
                asm volatile("ldmatrix.sync.aligned.m8n8.x4.shared.b16 {%0,%1,%2,%3}, [%4];"
                             : "=r"(b0), "=r"(b1), "=r"(b2r), "=r"(b3)
                             : "r"(cBb + offB[np] + kb));
#pragma unroll
                for (int mi = 0; mi < 2; mi++) {
                    mma_f16(c[mi][2 * np],     a[mi][0], a[mi][1], a[mi][2], a[mi][3], b0, b2r);
                    mma_f16(c[mi][2 * np + 1], a[mi][0], a[mi][1], a[mi][2], a[mi][3], b1, b3);
                }
            }
        }
        __syncthreads();
    }

#pragma unroll
    for (int mi = 0; mi < 2; mi++) {
        int r0 = row0 + wm * 32 + mi * 16 + g;
#pragma unroll
        for (int nf = 0; nf < 4; nf++) {
            int c0 = col0 + wn * 32 + nf * 8 + 2 * tq;
            float v0 = c[mi][nf][0], v1 = c[mi][nf][1];
            float v2 = c[mi][nf][2], v3 = c[mi][nf][3];
            if (relu) {
                v0 = fmaxf(v0, 0.f); v1 = fmaxf(v1, 0.f);
                v2 = fmaxf(v2, 0.f); v3 = fmaxf(v3, 0.f);
            }
            *(__half2*)&C[(size_t)r0 * N + c0]       = __floats2half2_rn(v0, v1);
            *(__half2*)&C[(size_t)(r0 + 8) * N + c0] = __floats2half2_rn(v2, v3);
        }
    }
}

// ============================================================================
// K3: logits[512,99999] = last_h[512,256] @ emb[1:].T  (FP16 mma m16n8k16)
//     R14-proven: 128x128 tile, 8 warps (4M x 2N), K-chunk 64 halves,
//     3-buffer mbarrier pipeline, ldmatrix.x4 fragments, fused LSE partials.
// ============================================================================
__device__ __forceinline__ void mbar_wait(uint32_t addr, uint32_t parity) {
    asm volatile(
        "{\n\t.reg .pred P;\n\t"
        "WL%=:\n\t"
        "mbarrier.try_wait.parity.acquire.cta.shared::cta.b64 P, [%0], %1, 0x989680;\n\t"
        "@P bra.uni DN%=;\n\t"
        "bra.uni WL%=;\n\t"
        "DN%=:\n\t}"
        :: "r"(addr), "r"(parity) : "memory");
}

#define PITCHB 144
#define STG_B (128 * PITCHB)
#define NST 3
#define NCHUNK 4
#define SM_CTRL 1024
#define SMEM_LOGITS_BYTES (SM_CTRL + 2 * NST * STG_B)   // 111616 B

__device__ __forceinline__ void stage_logits(uint32_t sA, uint32_t sB,
                                             const __half* __restrict__ Ah,
                                             const __half* __restrict__ embh,
                                             int mt, int nt, int k0, int t) {
#pragma unroll
    for (int u0 = 0; u0 < 4; u0++) {
        int u = t + u0 * 256;
        int r = u >> 3, c16 = u & 7;
        uint32_t da = sA + (uint32_t)(r * PITCHB + c16 * 16);
        const __half* srcA = Ah + (size_t)(mt + r) * DD + k0 + c16 * 8;
        asm volatile("cp.async.cg.shared.global [%0], [%1], 16;\n"
                     :: "r"(da), "l"(srcA));
        int er = nt + 1 + r;
        uint32_t db = sB + (uint32_t)(r * PITCHB + c16 * 16);
        const __half* srcB = embh + (size_t)(er < NN ? er : 0) * DD + k0 + c16 * 8;
        int sz = (er < NN) ? 16 : 0;
        asm volatile("cp.async.cg.shared.global [%0], [%1], 16, %2;\n"
                     :: "r"(db), "l"(srcB), "r"(sz));
    }
}

__global__ __launch_bounds__(256) void k_logits(const __half* __restrict__ Ah,
                                                const __half* __restrict__ embh,
                                                float* __restrict__ out) {
    extern __shared__ float smem[];
    uint32_t sbase = (uint32_t)__cvta_generic_to_shared(smem);
    uint32_t mfull[NST], mempty[NST];
#pragma unroll
    for (int i = 0; i < NST; i++) { mfull[i] = sbase + 16 * i; mempty[i] = sbase + 16 * i + 8; }
    uint32_t sA[NST], sB[NST];
#pragma unroll
    for (int i = 0; i < NST; i++) {
        sA[i] = sbase + SM_CTRL + i * STG_B;
        sB[i] = sbase + SM_CTRL + (NST + i) * STG_B;
    }

    int mt = blockIdx.x * 128;
    int nt = blockIdx.y * 128;
    int t = threadIdx.x;
    int warp = t >> 5, lane = t & 31;
    int wm = warp >> 1, wn = warp & 1;
    int g = lane >> 2, tq = lane & 3;
    int lr = lane & 7, bq = lane >> 3;
    int rowadd = lr + ((bq & 1) << 3);
    int coladdB = (bq >> 1) << 4;

    uint32_t offA[2], offB[4];
#pragma unroll
    for (int mi = 0; mi < 2; mi++)
        offA[mi] = (uint32_t)((wm * 32 + mi * 16 + rowadd) * PITCHB + coladdB);
#pragma unroll
    for (int np = 0; np < 4; np++)
        offB[np] = (uint32_t)((wn * 64 + np * 16 + rowadd) * PITCHB + coladdB);

    float c[2][8][4];
#pragma unroll
    for (int mi = 0; mi < 2; mi++)
#pragma unroll
        for (int ni = 0; ni < 8; ni++)
#pragma unroll
            for (int q = 0; q < 4; q++) c[mi][ni][q] = 0.f;

    if (t == 0) {
#pragma unroll
        for (int i = 0; i < NST; i++) {
            asm volatile("mbarrier.init.shared.b64 [%0], 256;" :: "r"(mfull[i])  : "memory");
            asm volatile("mbarrier.init.shared.b64 [%0], 8;"   :: "r"(mempty[i]) : "memory");
        }
    }
    __syncthreads();

    stage_logits(sA[0], sB[0], Ah, embh, mt, nt, 0, t);
    asm volatile("cp.async.mbarrier.arrive.noinc.shared.b64 [%0];" :: "r"(mfull[0]) : "memory");
    stage_logits(sA[1], sB[1], Ah, embh, mt, nt, 64, t);
    asm volatile("cp.async.mbarrier.arrive.noinc.shared.b64 [%0];" :: "r"(mfull[1]) : "memory");

    for (int s = 0; s < NCHUNK; s++) {
        int u = s + 2;
        if (u < NCHUNK) {
            int b2 = u % NST;
            if (u >= NST)
                mbar_wait(mempty[b2], (uint32_t)(((u - NST) / NST) & 1));
            stage_logits(sA[b2], sB[b2], Ah, embh, mt, nt, u * 64, t);
            asm volatile("cp.async.mbarrier.arrive.noinc.shared.b64 [%0];"
                         :: "r"(mfull[b2]) : "memory");
        }
        int b = s % NST;
        mbar_wait(mfull[b], (uint32_t)((s / NST) & 1));
        uint32_t cA = sA[b], cB = sB[b];
#pragma unroll
        for (int ks = 0; ks < 4; ks++) {
            uint32_t kb = (uint32_t)(ks * 32);
            uint32_t a[2][4];
#pragma unroll
            for (int mi = 0; mi < 2; mi++) {
                asm volatile("ldmatrix.sync.aligned.m8n8.x4.shared.b16 {%0,%1,%2,%3}, [%4];"
                             : "=r"(a[mi][0]), "=r"(a[mi][1]), "=r"(a[mi][2]), "=r"(a[mi][3])
                             : "r"(cA + offA[mi] + kb));
            }
#pragma unroll
            for (int np = 0; np < 4; np++) {
                uint32_t b0, b1, b2r, b3;
                asm volatile("ldmatrix.sync.aligned.m8n8.x4.shared.b16 {%0,%1,%2,%3}, [%4];"
                             : "=r"(b0), "=r"(b1), "=r"(b2r), "=r"(b3)
                             : "r"(cB + offB[np] + kb));
#pragma unroll
                for (int mi = 0; mi < 2; mi++) {
                    mma_f16(c[mi][2 * np],     a[mi][0], a[mi][1], a[mi][2], a[mi][3], b0, b2r);
                    mma_f16(c[mi][2 * np + 1], a[mi][0], a[mi][1], a[mi][2], a[mi][3], b1, b3);
                }
            }
        }
        if (lane == 0)
            asm volatile("mbarrier.arrive.shared.b64 _, [%0];" :: "r"(mempty[b]) : "memory");
    }

    // ---- logits stores ----
#pragma unroll
    for (int mi = 0; mi < 2; mi++) {
        int r0 = mt + wm * 32 + mi * 16 + g;
#pragma unroll
        for (int ni = 0; ni < 8; ni++) {
            int c0 = nt + wn * 64 + ni * 8 + 2 * tq;
            if (c0 < NM1) {
                out[(size_t)r0 * NM1 + c0]       = c[mi][ni][0];
                out[(size_t)(r0 + 8) * NM1 + c0] = c[mi][ni][2];
            }
            if (c0 + 1 < NM1) {
                out[(size_t)r0 * NM1 + c0 + 1]       = c[mi][ni][1];
                out[(size_t)(r0 + 8) * NM1 + c0 + 1] = c[mi][ni][3];
            }
        }
    }

    __syncthreads();

    // ---- fused LSE partials ----
    float* redM = smem + 256;
    float* redS = smem + 512;
#pragma unroll
    for (int slot = 0; slot < 4; slot++) {
        int mi = slot >> 1, h = slot & 1;
        float m = -3.0e38f;
#pragma unroll
        for (int ni = 0; ni < 8; ni++) {
            int cbase = nt + wn * 64 + ni * 8 + 2 * tq;
            float v0 = (cbase     < NM1) ? c[mi][ni][2 * h]     : -3.0e38f;
            float v1 = (cbase + 1 < NM1) ? c[mi][ni][2 * h + 1] : -3.0e38f;
            m = fmaxf(m, fmaxf(v0, v1));
        }
        float sum = 0.f;
#pragma unroll
        for (int ni = 0; ni < 8; ni++) {
            int cbase = nt + wn * 64 + ni * 8 + 2 * tq;
            float v0 = (cbase     < NM1) ? c[mi][ni][2 * h]     : -3.0e38f;
            float v1 = (cbase + 1 < NM1) ? c[mi][ni][2 * h + 1] : -3.0e38f;
            sum += __expf(v0 - m) + __expf(v1 - m);
        }
#pragma unroll
        for (int off = 1; off <= 2; off <<= 1) {
            float m2 = __shfl_xor_sync(0xffffffffu, m, off);
            float s2 = __shfl_xor_sync(0xffffffffu, sum, off);
            float M = fmaxf(m, m2);
            sum = sum * __expf(m - M) + s2 * __expf(m2 - M);
            m = M;
        }
        if (tq == 0) {
            redM[(warp * 4 + slot) * 8 + g] = m;
            redS[(warp * 4 + slot) * 8 + g] = sum;
        }
    }
    __syncthreads();
    if (t < 128) {
        int wmr = t >> 5, slot = (t >> 3) & 3, gg = t & 7;
        int i1 = ((wmr * 2)     * 4 + slot) * 8 + gg;
        int i2 = ((wmr * 2 + 1) * 4 + slot) * 8 + gg;
        float m1 = redM[i1], s1 = redS[i1];
        float m2 = redM[i2], s2 = redS[i2];
        float M = fmaxf(m1, m2);
        float S = s1 * __expf(m1 - M) + s2 * __expf(m2 - M);
        int row = mt + wmr * 32 + (slot >> 1) * 16 + (slot & 1) * 8 + gg;
        g_pmax[(size_t)row * NBLK + blockIdx.y] = M;
        g_psum[(size_t)row * NBLK + blockIdx.y] = S;
    }
}

// ============================================================================
// K4: finalize LSE from per-block partials
// ============================================================================
__global__ void k_lsefin(float* __restrict__ lse) {
    int b = blockIdx.x, t = threadIdx.x;
    float m = -3.0e38f, s = 0.f;
    for (int i = t; i < NBLK; i += 256) {
        float m2 = g_pmax[(size_t)b * NBLK + i];
        float s2 = g_psum[(size_t)b * NBLK + i];
        float M = fmaxf(m, m2);
        s = s * __expf(m - M) + s2 * __expf(m2 - M);
        m = M;
    }
    __shared__ float sm[256], ss[256];
    sm[t] = m; ss[t] = s;
    __syncthreads();
    for (int o = 128; o > 0; o >>= 1) {
        if (t < o) {
            float m2 = sm[t + o], s2 = ss[t + o];
            float M = fmaxf(sm[t], m2);
            ss[t] = ss[t] * __expf(sm[t] - M) + s2 * __expf(m2 - M);
            sm[t] = M;
        }
        __syncthreads();
    }
    if (t == 0) lse[b] = sm[0] + logf(ss[0]);
}

// ============================================================================
// K5: loss = -mean_b( logits[b, tar[b]-1] - lse[b] )
// ============================================================================
__global__ void k_loss(const float* __restrict__ logits, const float* __restrict__ lse,
                       const int* __restrict__ tar, float* __restrict__ loss_out) {
    __shared__ float red[512];
    int t = threadIdx.x;
    int tg = tar[t] - 1;
    red[t] = logits[(size_t)t * NM1 + tg] - lse[t];
    __syncthreads();
    for (int o = 256; o > 0; o >>= 1) {
        if (t < o) red[t] += red[t + o];
        __syncthreads();
    }
    if (t == 0) loss_out[0] = -red[0] / (float)BB;
}

// ============================================================================
// launch
// ============================================================================
extern "C" void kernel_launch(void* const* d_in, const int* in_sizes, int n_in,
                              void* d_out, int out_size) {
    const float* emb    = (const float*)d_in[0];
    const float* W1     = (const float*)d_in[1];
    const float* W2     = (const float*)d_in[2];
    const float* adjI   = (const float*)d_in[3];
    const float* adjO   = (const float*)d_in[4];
    const float* mask   = (const float*)d_in[5];
    const int*   item   = (const int*)d_in[6];
    const int*   alias_ = (const int*)d_in[7];
    const int*   tar    = (const int*)d_in[8];
    float* out = (float*)d_out;

    float *p_lse, *p_fb;
    __half *p_av, *p_hh, *p_lh, *p_eh, *p_w1t, *p_w2t;
    cudaGetSymbolAddress((void**)&p_av,  g_av_h);
    cudaGetSymbolAddress((void**)&p_hh,  g_h_h);
    cudaGetSymbolAddress((void**)&p_lh,  g_lasth_h);
    cudaGetSymbolAddress((void**)&p_eh,  g_emb_h);
    cudaGetSymbolAddress((void**)&p_w1t, g_W1t);
    cudaGetSymbolAddress((void**)&p_w2t, g_W2t);
    cudaGetSymbolAddress((void**)&p_lse, g_lse);
    cudaGetSymbolAddress((void**)&p_fb,  g_logits_fb);

    static int smem_set = 0;
    if (!smem_set) {
        cudaFuncSetAttribute(k_logits, cudaFuncAttributeMaxDynamicSharedMemorySize,
                             SMEM_LOGITS_BYTES);
        cudaFuncSetAttribute(k_gemm16, cudaFuncAttributeMaxDynamicSharedMemorySize,
                             SMEM_G16);
        smem_set = 1;
    }

    const long long NL = (long long)BB * NM1;
    float *loss_ptr, *logits_ptr;
    if ((long long)out_size >= NL + 1)      { loss_ptr = out;  logits_ptr = out + 1; }
    else if ((long long)out_size == NL)     { loss_ptr = p_fb; logits_ptr = out; }
    else                                    { loss_ptr = out;  logits_ptr = p_fb; }

    k_prep<<<2944, 256>>>(emb, W1, W2, adjI, adjO, mask, item, alias_);
    k_gemm16<<<dim3(D2 / 64, BB / 128), 256, SMEM_G16>>>(p_av, p_w1t, p_hh,
                                                         D2, D2, 1, 8);
    k_gemm16<<<dim3(DD / 64, BB / 128), 256, SMEM_G16>>>(p_hh, p_w2t, p_lh,
                                                         D2, DD, 0, 8);
    k_logits<<<dim3(4, NBLK), 256, SMEM_LOGITS_BYTES>>>(p_lh, p_eh, logits_ptr);
    k_lsefin<<<BB, 256>>>(p_lse);
    k_loss<<<1, 512>>>(logits_ptr, p_lse, tar, loss_ptr);
}